// round 6
// baseline (speedup 1.0000x reference)
#include <cuda_runtime.h>

// Shapes fixed by reference setup_inputs(): B=4, N=M=8192, D=3.
#define B_   4
#define N_   8192
#define M_   8192
#define S_   32                // splits of target range per direction
#define TPB  128
#define Q    4                 // query points per thread
#define TILE 256               // targets per CTA tile (== CHUNK)
#define UNITS (TILE / 2)       // 128 packed 2-target units
#define GRP8 (TILE / 8)        // 32 groups of 8 targets (5-bit group id)
#define CHUNK (M_ / S_)        // 256

#define NBLK_COMBINE (2 * B_ * N_ / 256)   // 256 blocks

// Scratch (no cudaMalloc). Layout is POINT-MAJOR: g_pk[point*S_ + s] so the
// combine kernel scans its 32 keys with 8 coalesced LDG.128. Key encodes
// masked value + 5-bit group id; group base = s*CHUNK + id*8.
__device__ float g_pk[2 * B_ * N_ * S_];   // 8 MB
__device__ float g_bs_d[NBLK_COMBINE];
__device__ float g_bs_n[NBLK_COMBINE];

typedef unsigned long long u64;

__device__ __forceinline__ u64 pk2(float lo, float hi) {
    u64 r; asm("mov.b64 %0, {%1, %2};" : "=l"(r) : "f"(lo), "f"(hi)); return r;
}
__device__ __forceinline__ void upk2(float& lo, float& hi, u64 v) {
    asm("mov.b64 {%0, %1}, %2;" : "=f"(lo), "=f"(hi) : "l"(v));
}
__device__ __forceinline__ u64 ffma2(u64 a, u64 b, u64 c) {
    u64 d; asm("fma.rn.f32x2 %0, %1, %2, %3;" : "=l"(d) : "l"(a), "l"(b), "l"(c));
    return d;
}

// ---------------------------------------------------------------------------
// Kernel 1: partial argmin of t = 0.5*|y|^2 - x.y over one 256-target tile.
// 8 targets per step via 4x f32x2 FFMA chains; 7-FMNMX scalar tree; ONE LOP3
// embeds the 5-bit group id in the low mantissa; one FMNMX keeps the running
// min. Winner = 8-target group; exact disambiguation in the combine kernel.
// blockIdx: (query block, split, dir*B+b)
// ---------------------------------------------------------------------------
__global__ __launch_bounds__(TPB, 8)
void chamfer_minpart_kernel(const float* __restrict__ x1,
                            const float* __restrict__ x2)
{
    const int dir = blockIdx.z / B_;
    const int b   = blockIdx.z % B_;
    const float* __restrict__ qry = dir ? x2 : x1;
    const float* __restrict__ tgt = dir ? x1 : x2;

    const int tid = threadIdx.x;
    const int q0  = blockIdx.x * (TPB * Q) + tid;

    u64 qxx[Q], qyy[Q], qzz[Q];
#pragma unroll
    for (int i = 0; i < Q; i++) {
        const float* g = qry + ((size_t)b * N_ + q0 + i * TPB) * 3;
        const float a = -g[0], bb = -g[1], c = -g[2];   // negated: pure FMA chain
        qxx[i] = pk2(a, a); qyy[i] = pk2(bb, bb); qzz[i] = pk2(c, c);
    }

    const int c0 = blockIdx.y * CHUNK;
    __shared__ ulonglong2 smA[UNITS];   // (x-pair, y-pair)
    __shared__ ulonglong2 smB[UNITS];   // (z-pair, halfnorm-pair)

    // fill the tile: 128 threads x 1 unit each (UNITS == TPB)
    {
        const int p = tid;
        const float* g = tgt + ((size_t)b * M_ + c0 + 2 * p) * 3;
        const float2 f0 = *(const float2*)(g);       // x0 y0
        const float2 f1 = *(const float2*)(g + 2);   // z0 x1
        const float2 f2 = *(const float2*)(g + 4);   // y1 z1
        const float w0 = 0.5f * (f0.x * f0.x + f0.y * f0.y + f1.x * f1.x);
        const float w1 = 0.5f * (f1.y * f1.y + f2.x * f2.x + f2.y * f2.y);
        smA[p] = make_ulonglong2(pk2(f0.x, f1.y), pk2(f0.y, f2.x));
        smB[p] = make_ulonglong2(pk2(f1.x, f2.y), pk2(w0, w1));
    }
    __syncthreads();

    float tk[Q];
#pragma unroll
    for (int i = 0; i < Q; i++) tk[i] = 3.3e38f;

#pragma unroll 1
    for (int up = 0; up < GRP8; up++) {
        const ulonglong2 A0 = smA[4 * up + 0];   // LDS.128 broadcast
        const ulonglong2 A1 = smA[4 * up + 1];
        const ulonglong2 A2 = smA[4 * up + 2];
        const ulonglong2 A3 = smA[4 * up + 3];
        const ulonglong2 B0 = smB[4 * up + 0];
        const ulonglong2 B1 = smB[4 * up + 1];
        const ulonglong2 B2 = smB[4 * up + 2];
        const ulonglong2 B3 = smB[4 * up + 3];
#pragma unroll
        for (int i = 0; i < Q; i++) {
            const u64 t0 = ffma2(qxx[i], A0.x, ffma2(qyy[i], A0.y, ffma2(qzz[i], B0.x, B0.y)));
            const u64 t1 = ffma2(qxx[i], A1.x, ffma2(qyy[i], A1.y, ffma2(qzz[i], B1.x, B1.y)));
            const u64 t2 = ffma2(qxx[i], A2.x, ffma2(qyy[i], A2.y, ffma2(qzz[i], B2.x, B2.y)));
            const u64 t3 = ffma2(qxx[i], A3.x, ffma2(qyy[i], A3.y, ffma2(qzz[i], B3.x, B3.y)));
            float l0, h0, l1, h1, l2, h2, l3, h3;
            upk2(l0, h0, t0); upk2(l1, h1, t1);
            upk2(l2, h2, t2); upk2(l3, h3, t3);
            const float m = fminf(fminf(fminf(l0, h0), fminf(l1, h1)),
                                  fminf(fminf(l2, h2), fminf(l3, h3)));
            const unsigned k = (__float_as_uint(m) & 0xFFFFFFE0u) | (unsigned)up;
            tk[i] = fminf(tk[i], __uint_as_float(k));
        }
    }

#pragma unroll
    for (int i = 0; i < Q; i++) {
        const size_t pnt = (size_t)(dir * B_ + b) * N_ + q0 + i * TPB;
        g_pk[pnt * S_ + blockIdx.y] = tk[i];
    }
}

// ---------------------------------------------------------------------------
// Kernel 2: scan this point's 32 keys (8 coalesced LDG.128; strict <,
// ascending s = first-occurrence ties), derive winning 8-target group base
// from split + key bits, recompute EXACT squared distances for the 8
// candidates, gather NN normal, cosine term, deterministic tree reduction.
// ---------------------------------------------------------------------------
__global__ __launch_bounds__(256)
void chamfer_combine_kernel(const float* __restrict__ x1,
                            const float* __restrict__ x2,
                            const float* __restrict__ n1,
                            const float* __restrict__ n2)
{
    const int tid = threadIdx.x;
    const int gid = blockIdx.x * 256 + tid;        // 0 .. 2*B*N-1
    const int dir = gid / (B_ * N_);
    const int r   = gid % (B_ * N_);
    const int b   = r / N_;
    const int n   = r % N_;

    const float* __restrict__ qryP = dir ? x2 : x1;
    const float* __restrict__ tgtP = dir ? x1 : x2;
    const float* __restrict__ qryN = dir ? n2 : n1;
    const float* __restrict__ tgtN = dir ? n1 : n2;

    // best split by key: 8 vectorized loads, strict ascending order
    const float4* kp = (const float4*)(g_pk + (size_t)gid * S_);
    float bk = 3.4e38f;
    int   bs = 0;
#pragma unroll
    for (int v = 0; v < S_ / 4; v++) {
        const float4 k4 = kp[v];
        if (k4.x < bk) { bk = k4.x; bs = 4 * v + 0; }
        if (k4.y < bk) { bk = k4.y; bs = 4 * v + 1; }
        if (k4.z < bk) { bk = k4.z; bs = 4 * v + 2; }
        if (k4.w < bk) { bk = k4.w; bs = 4 * v + 3; }
    }
    const int bbase = bs * CHUNK + (int)(__float_as_uint(bk) & 0x1Fu) * 8;

    const float* q = qryP + ((size_t)b * N_ + n) * 3;
    const float qx = q[0], qy = q[1], qz = q[2];

    // exact distances over the 8-candidate group
    float bestd = 3.4e38f;
    int   bidx  = bbase;
#pragma unroll
    for (int j = 0; j < 8; j++) {
        const int idx = bbase + j;
        const float* y = tgtP + ((size_t)b * M_ + idx) * 3;
        const float dx = qx - y[0], dy = qy - y[1], dz = qz - y[2];
        const float d = dx * dx + dy * dy + dz * dz;
        if (d < bestd) { bestd = d; bidx = idx; }
    }
    const float cham = bestd;                       // exact diff-form distance

    const float* a  = qryN + ((size_t)b * N_ + n) * 3;
    const float* nb = tgtN + ((size_t)b * M_ + bidx) * 3;
    const float dotp = a[0] * nb[0] + a[1] * nb[1] + a[2] * nb[2];
    float na_ = sqrtf(a[0] * a[0] + a[1] * a[1] + a[2] * a[2]);
    float nb_ = sqrtf(nb[0] * nb[0] + nb[1] * nb[1] + nb[2] * nb[2]);
    na_ = fmaxf(na_, 1e-6f);
    nb_ = fmaxf(nb_, 1e-6f);
    const float normterm = 1.0f - fabsf(dotp / (na_ * nb_));

    __shared__ float sd[256];
    __shared__ float sn[256];
    sd[tid] = cham;
    sn[tid] = normterm;
    __syncthreads();
#pragma unroll
    for (int o = 128; o > 0; o >>= 1) {
        if (tid < o) { sd[tid] += sd[tid + o]; sn[tid] += sn[tid + o]; }
        __syncthreads();
    }
    if (tid == 0) {
        g_bs_d[blockIdx.x] = sd[0];
        g_bs_n[blockIdx.x] = sn[0];
    }
}

// ---------------------------------------------------------------------------
// Kernel 3: final deterministic reduction (NBLK_COMBINE == 256 exactly).
// ---------------------------------------------------------------------------
__global__ __launch_bounds__(256)
void chamfer_final_kernel(float* __restrict__ out)
{
    __shared__ float sd[256];
    __shared__ float sn[256];
    const int tid = threadIdx.x;
    sd[tid] = g_bs_d[tid];
    sn[tid] = g_bs_n[tid];
    __syncthreads();
#pragma unroll
    for (int o = 128; o > 0; o >>= 1) {
        if (tid < o) { sd[tid] += sd[tid + o]; sn[tid] += sn[tid + o]; }
        __syncthreads();
    }
    if (tid == 0) {
        const float inv = 1.0f / (float)(B_ * N_);
        out[0] = sd[0] * inv;
        out[1] = sn[0] * inv;
    }
}

extern "C" void kernel_launch(void* const* d_in, const int* in_sizes, int n_in,
                              void* d_out, int out_size)
{
    const float* xyz1  = (const float*)d_in[0];
    const float* xyz2  = (const float*)d_in[1];
    const float* nxyz1 = (const float*)d_in[2];
    const float* nxyz2 = (const float*)d_in[3];
    float* out = (float*)d_out;

    dim3 grid1(N_ / (TPB * Q), S_, 2 * B_);   // (16, 32, 8) = 4096 CTAs
    chamfer_minpart_kernel<<<grid1, TPB>>>(xyz1, xyz2);

    chamfer_combine_kernel<<<NBLK_COMBINE, 256>>>(xyz1, xyz2, nxyz1, nxyz2);

    chamfer_final_kernel<<<1, 256>>>(out);
}

// round 7
// speedup vs baseline: 1.0487x; 1.0487x over previous
#include <cuda_runtime.h>

// Shapes fixed by reference setup_inputs(): B=4, N=M=8192, D=3.
#define B_   4
#define N_   8192
#define M_   8192
#define S_   32                // splits of target range per direction
#define TPB  128
#define Q    4                 // query points per thread
#define TILE 256               // targets per CTA tile (== CHUNK)
#define UNITS (TILE / 2)       // 128 packed 2-target units
#define GRP8 (TILE / 8)        // 32 groups of 8 targets (5-bit group id)
#define CHUNK (M_ / S_)        // 256

#define NBLK_COMBINE (2 * B_ * N_ / 256)   // 256 blocks

// Scratch (no cudaMalloc). SPLIT-MAJOR layout (coalesced minpart stores):
// g_pk[((dir*S+s)*B+b)*N + n]. Key = masked value | 5-bit group id;
// winning group base = s*CHUNK + id*8, so no index array needed.
__device__ float g_pk[2 * S_ * B_ * N_];   // 8 MB
__device__ float g_bs_d[NBLK_COMBINE];
__device__ float g_bs_n[NBLK_COMBINE];

typedef unsigned long long u64;

__device__ __forceinline__ u64 pk2(float lo, float hi) {
    u64 r; asm("mov.b64 %0, {%1, %2};" : "=l"(r) : "f"(lo), "f"(hi)); return r;
}
__device__ __forceinline__ void upk2(float& lo, float& hi, u64 v) {
    asm("mov.b64 {%0, %1}, %2;" : "=f"(lo), "=f"(hi) : "l"(v));
}
__device__ __forceinline__ u64 ffma2(u64 a, u64 b, u64 c) {
    u64 d; asm("fma.rn.f32x2 %0, %1, %2, %3;" : "=l"(d) : "l"(a), "l"(b), "l"(c));
    return d;
}

// ---------------------------------------------------------------------------
// Kernel 1: partial argmin of t = 0.5*|y|^2 - x.y over one 256-target tile.
// 8 targets per step via 4x f32x2 FFMA chains, scheduled in STAGES so that
// consecutive FFMA2s share their slot-0 multiplier (qzz, then qyy, then qxx)
// -> operand-reuse cache drops the RF-bank reciprocal throughput of FFMA2
// from 3 to 2 cycles. 7-FMNMX tree + LOP3 id-embed + running FMNMX as before.
// blockIdx: (query block, split, dir*B+b)
// ---------------------------------------------------------------------------
__global__ __launch_bounds__(TPB, 7)
void chamfer_minpart_kernel(const float* __restrict__ x1,
                            const float* __restrict__ x2)
{
    const int dir = blockIdx.z / B_;
    const int b   = blockIdx.z % B_;
    const float* __restrict__ qry = dir ? x2 : x1;
    const float* __restrict__ tgt = dir ? x1 : x2;

    const int tid = threadIdx.x;
    const int q0  = blockIdx.x * (TPB * Q) + tid;

    u64 qxx[Q], qyy[Q], qzz[Q];
#pragma unroll
    for (int i = 0; i < Q; i++) {
        const float* g = qry + ((size_t)b * N_ + q0 + i * TPB) * 3;
        const float a = -g[0], bb = -g[1], c = -g[2];   // negated: pure FMA chain
        qxx[i] = pk2(a, a); qyy[i] = pk2(bb, bb); qzz[i] = pk2(c, c);
    }

    const int c0 = blockIdx.y * CHUNK;
    __shared__ ulonglong2 smA[UNITS];   // (x-pair, y-pair)
    __shared__ ulonglong2 smB[UNITS];   // (z-pair, halfnorm-pair)

    // fill the tile: 128 threads x 1 unit each (UNITS == TPB)
    {
        const int p = tid;
        const float* g = tgt + ((size_t)b * M_ + c0 + 2 * p) * 3;
        const float2 f0 = *(const float2*)(g);       // x0 y0
        const float2 f1 = *(const float2*)(g + 2);   // z0 x1
        const float2 f2 = *(const float2*)(g + 4);   // y1 z1
        const float w0 = 0.5f * (f0.x * f0.x + f0.y * f0.y + f1.x * f1.x);
        const float w1 = 0.5f * (f1.y * f1.y + f2.x * f2.x + f2.y * f2.y);
        smA[p] = make_ulonglong2(pk2(f0.x, f1.y), pk2(f0.y, f2.x));
        smB[p] = make_ulonglong2(pk2(f1.x, f2.y), pk2(w0, w1));
    }
    __syncthreads();

    float tk[Q];
#pragma unroll
    for (int i = 0; i < Q; i++) tk[i] = 3.3e38f;

#pragma unroll 1
    for (int up = 0; up < GRP8; up++) {
        const ulonglong2 A0 = smA[4 * up + 0];   // LDS.128 broadcast
        const ulonglong2 A1 = smA[4 * up + 1];
        const ulonglong2 A2 = smA[4 * up + 2];
        const ulonglong2 A3 = smA[4 * up + 3];
        const ulonglong2 B0 = smB[4 * up + 0];
        const ulonglong2 B1 = smB[4 * up + 1];
        const ulonglong2 B2 = smB[4 * up + 2];
        const ulonglong2 B3 = smB[4 * up + 3];
#pragma unroll
        for (int i = 0; i < Q; i++) {
            // stage 0: shared multiplier qzz[i] across 4 consecutive FFMA2s
            u64 s0 = ffma2(qzz[i], B0.x, B0.y);
            u64 s1 = ffma2(qzz[i], B1.x, B1.y);
            u64 s2 = ffma2(qzz[i], B2.x, B2.y);
            u64 s3 = ffma2(qzz[i], B3.x, B3.y);
            // stage 1: shared multiplier qyy[i]
            s0 = ffma2(qyy[i], A0.y, s0);
            s1 = ffma2(qyy[i], A1.y, s1);
            s2 = ffma2(qyy[i], A2.y, s2);
            s3 = ffma2(qyy[i], A3.y, s3);
            // stage 2: shared multiplier qxx[i]
            s0 = ffma2(qxx[i], A0.x, s0);
            s1 = ffma2(qxx[i], A1.x, s1);
            s2 = ffma2(qxx[i], A2.x, s2);
            s3 = ffma2(qxx[i], A3.x, s3);

            float l0, h0, l1, h1, l2, h2, l3, h3;
            upk2(l0, h0, s0); upk2(l1, h1, s1);
            upk2(l2, h2, s2); upk2(l3, h3, s3);
            const float m = fminf(fminf(fminf(l0, h0), fminf(l1, h1)),
                                  fminf(fminf(l2, h2), fminf(l3, h3)));
            const unsigned k = (__float_as_uint(m) & 0xFFFFFFE0u) | (unsigned)up;
            tk[i] = fminf(tk[i], __uint_as_float(k));
        }
    }

#pragma unroll
    for (int i = 0; i < Q; i++) {
        const size_t o = (((size_t)(dir * S_ + blockIdx.y) * B_ + b) * N_) + q0 + i * TPB;
        g_pk[o] = tk[i];
    }
}

// ---------------------------------------------------------------------------
// Kernel 2: scan this point's 32 keys (strict <, ascending s =
// first-occurrence ties), derive winning 8-target group base from split +
// key bits, recompute EXACT squared distances for the 8 candidates, gather
// NN normal, cosine term, deterministic tree reduction.
// ---------------------------------------------------------------------------
__global__ __launch_bounds__(256)
void chamfer_combine_kernel(const float* __restrict__ x1,
                            const float* __restrict__ x2,
                            const float* __restrict__ n1,
                            const float* __restrict__ n2)
{
    const int tid = threadIdx.x;
    const int gid = blockIdx.x * 256 + tid;        // 0 .. 2*B*N-1
    const int dir = gid / (B_ * N_);
    const int r   = gid % (B_ * N_);
    const int b   = r / N_;
    const int n   = r % N_;

    const float* __restrict__ qryP = dir ? x2 : x1;
    const float* __restrict__ tgtP = dir ? x1 : x2;
    const float* __restrict__ qryN = dir ? n2 : n1;
    const float* __restrict__ tgtN = dir ? n1 : n2;

    // best split by key (ascending s, strict <)
    float bk = 3.4e38f;
    int   bs = 0;
#pragma unroll
    for (int s = 0; s < S_; s++) {
        const float k = g_pk[(((size_t)(dir * S_ + s) * B_ + b) * N_) + n];
        if (k < bk) { bk = k; bs = s; }
    }
    const int bbase = bs * CHUNK + (int)(__float_as_uint(bk) & 0x1Fu) * 8;

    const float* q = qryP + ((size_t)b * N_ + n) * 3;
    const float qx = q[0], qy = q[1], qz = q[2];

    // exact distances over the 8-candidate group
    float bestd = 3.4e38f;
    int   bidx  = bbase;
#pragma unroll
    for (int j = 0; j < 8; j++) {
        const int idx = bbase + j;
        const float* y = tgtP + ((size_t)b * M_ + idx) * 3;
        const float dx = qx - y[0], dy = qy - y[1], dz = qz - y[2];
        const float d = dx * dx + dy * dy + dz * dz;
        if (d < bestd) { bestd = d; bidx = idx; }
    }
    const float cham = bestd;                       // exact diff-form distance

    const float* a  = qryN + ((size_t)b * N_ + n) * 3;
    const float* nb = tgtN + ((size_t)b * M_ + bidx) * 3;
    const float dotp = a[0] * nb[0] + a[1] * nb[1] + a[2] * nb[2];
    float na_ = sqrtf(a[0] * a[0] + a[1] * a[1] + a[2] * a[2]);
    float nb_ = sqrtf(nb[0] * nb[0] + nb[1] * nb[1] + nb[2] * nb[2]);
    na_ = fmaxf(na_, 1e-6f);
    nb_ = fmaxf(nb_, 1e-6f);
    const float normterm = 1.0f - fabsf(dotp / (na_ * nb_));

    __shared__ float sd[256];
    __shared__ float sn[256];
    sd[tid] = cham;
    sn[tid] = normterm;
    __syncthreads();
#pragma unroll
    for (int o = 128; o > 0; o >>= 1) {
        if (tid < o) { sd[tid] += sd[tid + o]; sn[tid] += sn[tid + o]; }
        __syncthreads();
    }
    if (tid == 0) {
        g_bs_d[blockIdx.x] = sd[0];
        g_bs_n[blockIdx.x] = sn[0];
    }
}

// ---------------------------------------------------------------------------
// Kernel 3: final deterministic reduction (NBLK_COMBINE == 256 exactly).
// ---------------------------------------------------------------------------
__global__ __launch_bounds__(256)
void chamfer_final_kernel(float* __restrict__ out)
{
    __shared__ float sd[256];
    __shared__ float sn[256];
    const int tid = threadIdx.x;
    sd[tid] = g_bs_d[tid];
    sn[tid] = g_bs_n[tid];
    __syncthreads();
#pragma unroll
    for (int o = 128; o > 0; o >>= 1) {
        if (tid < o) { sd[tid] += sd[tid + o]; sn[tid] += sn[tid + o]; }
        __syncthreads();
    }
    if (tid == 0) {
        const float inv = 1.0f / (float)(B_ * N_);
        out[0] = sd[0] * inv;
        out[1] = sn[0] * inv;
    }
}

extern "C" void kernel_launch(void* const* d_in, const int* in_sizes, int n_in,
                              void* d_out, int out_size)
{
    const float* xyz1  = (const float*)d_in[0];
    const float* xyz2  = (const float*)d_in[1];
    const float* nxyz1 = (const float*)d_in[2];
    const float* nxyz2 = (const float*)d_in[3];
    float* out = (float*)d_out;

    dim3 grid1(N_ / (TPB * Q), S_, 2 * B_);   // (16, 32, 8) = 4096 CTAs
    chamfer_minpart_kernel<<<grid1, TPB>>>(xyz1, xyz2);

    chamfer_combine_kernel<<<NBLK_COMBINE, 256>>>(xyz1, xyz2, nxyz1, nxyz2);

    chamfer_final_kernel<<<1, 256>>>(out);
}